// round 4
// baseline (speedup 1.0000x reference)
#include <cuda_runtime.h>

#define MAX_N 100000
#define MAX_E 1600000

// ---------------- scratch (static __device__ arrays) ----------------------
__device__ float g_h1  [MAX_N * 64];
__device__ float g_als1[MAX_N * 4];
__device__ float g_ald1[MAX_N * 4];
__device__ float g_out1[MAX_N * 64];
__device__ float g_h2  [MAX_N * 128];
__device__ float g_als2[MAX_N * 4];
__device__ float g_ald2[MAX_N * 4];
__device__ int   g_rowptr[MAX_N + 1];
__device__ int   g_cursor[MAX_N];
__device__ int   g_bsum[128];
__device__ int   g_ssrc[MAX_E];

// ---------------- GEMM: C[M,NC] = A[M,K] @ W[K,NC] ------------------------
// tile 128 x NC, micro 8x8, 16*(NC/8) threads, reg-prefetch double buffer.
template<int K, int NC>
__global__ __launch_bounds__(16 * (NC / 8))
void gemm_kernel(const float* __restrict__ A, const float* __restrict__ W,
                 float* __restrict__ C, int M)
{
    constexpr int KC = 32;
    constexpr int TX = NC / 8;          // 8 (NC=64) or 16 (NC=128)
    constexpr int T  = 16 * TX;         // 128 or 256 threads
    constexpr int A_F4 = (128 * KC / 4) / T;  // 8 or 4
    constexpr int B_F4 = (KC * NC / 4) / T;   // 4

    __shared__ float As[128][33];       // row-major, pad 33: conflict-free
    __shared__ float Bs[KC][NC];

    const int tid = threadIdx.x;
    const int tx = tid % TX;
    const int ty = tid / TX;
    const int row0 = blockIdx.x * 128;

    float4 aPre[A_F4], bPre[B_F4];

    auto loadA = [&](int kk) {
#pragma unroll
        for (int t = 0; t < A_F4; t++) {
            int q = tid + t * T;          // 0..1023
            int r = q >> 3, kc4 = q & 7;
            int gr = row0 + r;
            aPre[t] = (gr < M)
                ? *(const float4*)(A + (size_t)gr * K + kk + kc4 * 4)
                : make_float4(0.f, 0.f, 0.f, 0.f);
        }
    };
    auto loadB = [&](int kk) {
#pragma unroll
        for (int t = 0; t < B_F4; t++) {
            int q = tid + t * T;
            int r = q / (NC / 4), c4 = q % (NC / 4);
            bPre[t] = *(const float4*)(W + (size_t)(kk + r) * NC + c4 * 4);
        }
    };
    auto storeA = [&]() {
#pragma unroll
        for (int t = 0; t < A_F4; t++) {
            int q = tid + t * T;
            int r = q >> 3, kc4 = q & 7;
            As[r][kc4 * 4 + 0] = aPre[t].x;
            As[r][kc4 * 4 + 1] = aPre[t].y;
            As[r][kc4 * 4 + 2] = aPre[t].z;
            As[r][kc4 * 4 + 3] = aPre[t].w;
        }
    };
    auto storeB = [&]() {
#pragma unroll
        for (int t = 0; t < B_F4; t++) {
            int q = tid + t * T;
            int r = q / (NC / 4), c4 = q % (NC / 4);
            *(float4*)&Bs[r][c4 * 4] = bPre[t];
        }
    };

    float acc[8][8];
#pragma unroll
    for (int i = 0; i < 8; i++)
#pragma unroll
        for (int j = 0; j < 8; j++) acc[i][j] = 0.f;

    loadA(0); loadB(0);
    storeA(); storeB();
    __syncthreads();

    for (int kk = KC; kk <= K; kk += KC) {
        const bool more = (kk < K);
        if (more) { loadA(kk); loadB(kk); }

#pragma unroll
        for (int k = 0; k < KC; k++) {
            float a[8];
#pragma unroll
            for (int i = 0; i < 8; i++) a[i] = As[ty * 8 + i][k];
            float4 b0 = *(float4*)&Bs[k][tx * 8];
            float4 b1 = *(float4*)&Bs[k][tx * 8 + 4];
#pragma unroll
            for (int i = 0; i < 8; i++) {
                acc[i][0] = fmaf(a[i], b0.x, acc[i][0]);
                acc[i][1] = fmaf(a[i], b0.y, acc[i][1]);
                acc[i][2] = fmaf(a[i], b0.z, acc[i][2]);
                acc[i][3] = fmaf(a[i], b0.w, acc[i][3]);
                acc[i][4] = fmaf(a[i], b1.x, acc[i][4]);
                acc[i][5] = fmaf(a[i], b1.y, acc[i][5]);
                acc[i][6] = fmaf(a[i], b1.z, acc[i][6]);
                acc[i][7] = fmaf(a[i], b1.w, acc[i][7]);
            }
        }
        __syncthreads();
        if (more) {
            storeA(); storeB();
            __syncthreads();
        }
    }

#pragma unroll
    for (int i = 0; i < 8; i++) {
        int gr = row0 + ty * 8 + i;
        if (gr < M) {
            *(float4*)(C + (size_t)gr * NC + tx * 8) =
                make_float4(acc[i][0], acc[i][1], acc[i][2], acc[i][3]);
            *(float4*)(C + (size_t)gr * NC + tx * 8 + 4) =
                make_float4(acc[i][4], acc[i][5], acc[i][6], acc[i][7]);
        }
    }
}

// ---------------- attention logits ----------------------------------------
template<int C>
__global__ void al_kernel(const float* __restrict__ h,
                          const float* __restrict__ a_src,
                          const float* __restrict__ a_dst,
                          float* __restrict__ als, float* __restrict__ ald, int n)
{
    int t = blockIdx.x * blockDim.x + threadIdx.x;
    if (t >= n * 4) return;
    int node = t >> 2, head = t & 3;
    const float* hp  = h + (size_t)node * (4 * C) + head * C;
    const float* asp = a_src + head * C;
    const float* adp = a_dst + head * C;
    float s1 = 0.f, s2 = 0.f;
#pragma unroll
    for (int c = 0; c < C; c += 4) {
        float4 hv = *(const float4*)(hp + c);
        float4 av = *(const float4*)(asp + c);
        float4 dv = *(const float4*)(adp + c);
        s1 += hv.x * av.x + hv.y * av.y + hv.z * av.z + hv.w * av.w;
        s2 += hv.x * dv.x + hv.y * dv.y + hv.z * dv.z + hv.w * dv.w;
    }
    als[t] = s1;
    ald[t] = s2;
}

// ---------------- CSR build ------------------------------------------------
__global__ void hist_kernel(const int* __restrict__ de, int E, int* __restrict__ cnt)
{
    int e = blockIdx.x * blockDim.x + threadIdx.x;
    if (e < E) atomicAdd(&cnt[de[e]], 1);
}

__global__ void scan_k1(int* __restrict__ data, int n, int* __restrict__ bsum)
{
    __shared__ int sh[256];
    int base = blockIdx.x * 2048 + threadIdx.x * 8;
    int v[8];
    int run = 0;
#pragma unroll
    for (int k = 0; k < 8; k++) {
        int t = (base + k < n) ? data[base + k] : 0;
        v[k] = run;
        run += t;
    }
    sh[threadIdx.x] = run;
    __syncthreads();
    for (int off = 1; off < 256; off <<= 1) {
        int t = (threadIdx.x >= off) ? sh[threadIdx.x - off] : 0;
        __syncthreads();
        sh[threadIdx.x] += t;
        __syncthreads();
    }
    int excl = sh[threadIdx.x] - run;
#pragma unroll
    for (int k = 0; k < 8; k++)
        if (base + k < n) data[base + k] = v[k] + excl;
    if (threadIdx.x == 255) bsum[blockIdx.x] = sh[255];
}

__global__ void scan_k2(int* __restrict__ bsum, int nb)
{
    if (threadIdx.x == 0) {
        int run = 0;
        for (int i = 0; i < nb; i++) { int t = bsum[i]; bsum[i] = run; run += t; }
    }
}

__global__ void scan_k3(int* __restrict__ data, int n, const int* __restrict__ bsum,
                        int* __restrict__ cursor, int E)
{
    int i = blockIdx.x * blockDim.x + threadIdx.x;
    if (i < n) {
        int v = data[i] + bsum[i >> 11];
        data[i] = v;
        cursor[i] = v;
    }
    if (i == 0) data[n] = E;
}

__global__ void scatter_kernel(const int* __restrict__ se, const int* __restrict__ de,
                               int E, int* __restrict__ cursor, int* __restrict__ ssrc)
{
    int e = blockIdx.x * blockDim.x + threadIdx.x;
    if (e < E) {
        int pos = atomicAdd(&cursor[de[e]], 1);
        ssrc[pos] = se[e];
    }
}

// ---------------- fused softmax-aggregate, CSR (layer 1) -------------------
template<int C>
__global__ void agg_csr_kernel(const int* __restrict__ rowptr,
                               const int* __restrict__ ssrc,
                               const float* __restrict__ als,
                               const float* __restrict__ ald,
                               const float* __restrict__ h,
                               const float* __restrict__ bias,
                               float* __restrict__ out, int n)
{
    constexpr int HC = 4 * C;
    constexpr int G  = HC / 4;
    int gt   = blockIdx.x * blockDim.x + threadIdx.x;
    int node = gt / G;
    int li   = gt % G;
    if (node >= n) return;
    int head = li / (C / 4);

    float aldv = ald[(size_t)node * 4 + head];

    float e0 = als[(size_t)node * 4 + head] + aldv;
    e0 = e0 > 0.f ? e0 : 0.2f * e0;
    float ex = __expf(e0);
    float den = ex;
    float4 hv = ((const float4*)(h + (size_t)node * HC))[li];
    float4 acc = make_float4(ex * hv.x, ex * hv.y, ex * hv.z, ex * hv.w);

    int j1 = rowptr[node + 1];
    for (int j = rowptr[node]; j < j1; j++) {
        int s = ssrc[j];
        float e = als[(size_t)s * 4 + head] + aldv;
        e = e > 0.f ? e : 0.2f * e;
        float w = __expf(e);
        den += w;
        float4 v = ((const float4*)(h + (size_t)s * HC))[li];
        acc.x = fmaf(w, v.x, acc.x);
        acc.y = fmaf(w, v.y, acc.y);
        acc.z = fmaf(w, v.z, acc.z);
        acc.w = fmaf(w, v.w, acc.w);
    }
    float inv = 1.f / den;
    float4 o;
    o.x = acc.x * inv + bias[li * 4 + 0];
    o.y = acc.y * inv + bias[li * 4 + 1];
    o.z = acc.z * inv + bias[li * 4 + 2];
    o.w = acc.w * inv + bias[li * 4 + 3];
    ((float4*)(out + (size_t)node * HC))[li] = o;
}

// ---------------- layer 2: aggregate + head-mean + bias + elu + logsoftmax -
__global__ void agg2_final_kernel(const int* __restrict__ rowptr,
                                  const int* __restrict__ ssrc,
                                  const float* __restrict__ als,
                                  const float* __restrict__ ald,
                                  const float* __restrict__ h,
                                  const float* __restrict__ b2,
                                  float* __restrict__ y, int n)
{
    int lane = threadIdx.x & 31;
    int node = (blockIdx.x * blockDim.x + threadIdx.x) >> 5;
    if (node >= n) return;
    int head = lane >> 3;

    float aldv = ald[(size_t)node * 4 + head];

    float e0 = als[(size_t)node * 4 + head] + aldv;
    e0 = e0 > 0.f ? e0 : 0.2f * e0;
    float ex = __expf(e0);
    float den = ex;
    float4 hv = ((const float4*)(h + (size_t)node * 128))[lane];
    float4 acc = make_float4(ex * hv.x, ex * hv.y, ex * hv.z, ex * hv.w);

    int j1 = rowptr[node + 1];
    for (int j = rowptr[node]; j < j1; j++) {
        int s = ssrc[j];
        float e = als[(size_t)s * 4 + head] + aldv;
        e = e > 0.f ? e : 0.2f * e;
        float w = __expf(e);
        den += w;
        float4 v = ((const float4*)(h + (size_t)s * 128))[lane];
        acc.x = fmaf(w, v.x, acc.x);
        acc.y = fmaf(w, v.y, acc.y);
        acc.z = fmaf(w, v.z, acc.z);
        acc.w = fmaf(w, v.w, acc.w);
    }
    float inv = 1.f / den;
    float4 v = make_float4(acc.x * inv, acc.y * inv, acc.z * inv, acc.w * inv);

    v.x += __shfl_xor_sync(0xffffffffu, v.x, 8);
    v.y += __shfl_xor_sync(0xffffffffu, v.y, 8);
    v.z += __shfl_xor_sync(0xffffffffu, v.z, 8);
    v.w += __shfl_xor_sync(0xffffffffu, v.w, 8);
    v.x += __shfl_xor_sync(0xffffffffu, v.x, 16);
    v.y += __shfl_xor_sync(0xffffffffu, v.y, 16);
    v.z += __shfl_xor_sync(0xffffffffu, v.z, 16);
    v.w += __shfl_xor_sync(0xffffffffu, v.w, 16);
    int c0 = (lane & 7) * 4;
    v.x = 0.25f * v.x + b2[c0 + 0];
    v.y = 0.25f * v.y + b2[c0 + 1];
    v.z = 0.25f * v.z + b2[c0 + 2];
    v.w = 0.25f * v.w + b2[c0 + 3];
    v.x = v.x > 0.f ? v.x : expm1f(v.x);
    v.y = v.y > 0.f ? v.y : expm1f(v.y);
    v.z = v.z > 0.f ? v.z : expm1f(v.z);
    v.w = v.w > 0.f ? v.w : expm1f(v.w);
    float m = fmaxf(fmaxf(v.x, v.y), fmaxf(v.z, v.w));
#pragma unroll
    for (int off = 1; off < 8; off <<= 1)
        m = fmaxf(m, __shfl_xor_sync(0xffffffffu, m, off));
    float s = expf(v.x - m) + expf(v.y - m) + expf(v.z - m) + expf(v.w - m);
#pragma unroll
    for (int off = 1; off < 8; off <<= 1)
        s += __shfl_xor_sync(0xffffffffu, s, off);
    float ls = m + logf(s);
    if (lane < 8) {
        float4 o = make_float4(v.x - ls, v.y - ls, v.z - ls, v.w - ls);
        ((float4*)(y + (size_t)node * 32))[lane] = o;
    }
}

// ---------------------------------------------------------------------------
extern "C" void kernel_launch(void* const* d_in, const int* in_sizes, int n_in,
                              void* d_out, int out_size)
{
    const float* x   = (const float*)d_in[0];
    const int*   ei  = (const int*)d_in[1];
    const float* W1  = (const float*)d_in[2];
    const float* as1 = (const float*)d_in[3];
    const float* ad1 = (const float*)d_in[4];
    const float* b1  = (const float*)d_in[5];
    const float* W2  = (const float*)d_in[6];
    const float* as2 = (const float*)d_in[7];
    const float* ad2 = (const float*)d_in[8];
    const float* b2  = (const float*)d_in[9];
    float*       y   = (float*)d_out;

    const int n = in_sizes[0] / 128;
    const int E = in_sizes[1] / 2;
    const int* se = ei;
    const int* de = ei + E;

    float *h1, *als1, *ald1, *out1, *h2, *als2, *ald2;
    int *rowptr, *cursor, *bsum, *ssrc;
    cudaGetSymbolAddress((void**)&h1,     g_h1);
    cudaGetSymbolAddress((void**)&als1,   g_als1);
    cudaGetSymbolAddress((void**)&ald1,   g_ald1);
    cudaGetSymbolAddress((void**)&out1,   g_out1);
    cudaGetSymbolAddress((void**)&h2,     g_h2);
    cudaGetSymbolAddress((void**)&als2,   g_als2);
    cudaGetSymbolAddress((void**)&ald2,   g_ald2);
    cudaGetSymbolAddress((void**)&rowptr, g_rowptr);
    cudaGetSymbolAddress((void**)&cursor, g_cursor);
    cudaGetSymbolAddress((void**)&bsum,   g_bsum);
    cudaGetSymbolAddress((void**)&ssrc,   g_ssrc);

    // side stream + events, created once (first call is the uncaptured
    // correctness run; later captured calls just reuse them)
    static cudaStream_t s2 = nullptr;
    static cudaEvent_t evFork = nullptr, evJoin = nullptr;
    if (!s2) {
        cudaStreamCreateWithFlags(&s2, cudaStreamNonBlocking);
        cudaEventCreateWithFlags(&evFork, cudaEventDisableTiming);
        cudaEventCreateWithFlags(&evJoin, cudaEventDisableTiming);
    }

    const int nb = (n + 2047) / 2048;

    // ---- fork: CSR build on s2, concurrent with GEMM1 + al1 ----
    cudaEventRecord(evFork, 0);
    cudaStreamWaitEvent(s2, evFork, 0);
    cudaMemsetAsync(rowptr, 0, (size_t)n * sizeof(int), s2);
    hist_kernel<<<(E + 255) / 256, 256, 0, s2>>>(de, E, rowptr);
    scan_k1<<<nb, 256, 0, s2>>>(rowptr, n, bsum);
    scan_k2<<<1, 32, 0, s2>>>(bsum, nb);
    scan_k3<<<(n + 255) / 256, 256, 0, s2>>>(rowptr, n, bsum, cursor, E);
    scatter_kernel<<<(E + 255) / 256, 256, 0, s2>>>(se, de, E, cursor, ssrc);
    cudaEventRecord(evJoin, s2);

    // ---- layer 1 dense part (main stream, overlapped with CSR) ----
    gemm_kernel<128, 64><<<(n + 127) / 128, 128>>>(x, W1, h1, n);
    al_kernel<16><<<(n * 4 + 255) / 256, 256>>>(h1, as1, ad1, als1, ald1, n);

    // ---- join, then edge passes ----
    cudaStreamWaitEvent(0, evJoin, 0);
    agg_csr_kernel<16><<<(int)(((long long)n * 16 + 255) / 256), 256>>>(
        rowptr, ssrc, als1, ald1, h1, b1, out1, n);

    // ---- layer 2 ----
    gemm_kernel<64, 128><<<(n + 127) / 128, 256>>>(out1, W2, h2, n);
    al_kernel<32><<<(n * 4 + 255) / 256, 256>>>(h2, as2, ad2, als2, ald2, n);
    agg2_final_kernel<<<(int)(((long long)n * 32 + 255) / 256), 256>>>(
        rowptr, ssrc, als2, ald2, h2, b2, y, n);
}